// round 7
// baseline (speedup 1.0000x reference)
#include <cuda_runtime.h>
#include <cuda_fp16.h>
#include <cstdint>

// SpatialDeformer3D: trilinear warp of X[...,0] by per-voxel deformation.
// Shapes fixed: B=2, H=160, W=192, D=160.
//
// R7 (ncu: L1tex 74.8% binder, DRAM 26.7%):
//  - compact X channel-0 to FP16 (19.7 MB, L2-resident; tolerance is 1e-3,
//    fp16 conversion error ~2.4e-4, weights stay fp32)
//    -> gather LDG line span halves: ~2.5 -> ~1.3 lines per warp gather
//  - 1 voxel/thread (warp = 32 consecutive z, all lanes share (x,y))
//  - deformation staged through shared memory: coalesced float4 loads +
//    conflict-free stride-3 LDS (9 scalar-LDG wf -> ~6 wf per 32 voxels)

namespace {
constexpr int B  = 2;
constexpr int H  = 160;
constexpr int W  = 192;
constexpr int D  = 160;
constexpr int WD = W * D;            // 30720
constexpr int N  = H * W * D;        // 4,915,200 per batch
constexpr int NT = B * N;            // 9,830,400 total voxels
constexpr int THREADS = 256;
constexpr int MAIN_BLOCKS = NT / THREADS;       // 38400 (exact)
constexpr int PRE_ITEMS   = NT / 8;             // 8 voxels per pre-pass thread
}

// Compacted fp16 channel-0 volume (19.7 MB). Static scratch (no allocs).
__device__ __half g_xh[NT];

// ---------------------------------------------------------------------------
// Pre-pass: X interleaved f32 (ch0,ch1) -> g_xh fp16 (ch0). 8 voxels/thread.
__global__ void __launch_bounds__(256)
compact_kernel(const float4* __restrict__ X4) {
    int i = blockIdx.x * blockDim.x + threadIdx.x;   // [0, NT/8)
    if (i >= PRE_ITEMS) return;
    float4 a = X4[4 * i + 0];   // voxels 8i+0,8i+1 (ch0,ch1,ch0,ch1)
    float4 b = X4[4 * i + 1];
    float4 c = X4[4 * i + 2];
    float4 d = X4[4 * i + 3];
    __half2 h[4];
    h[0] = __floats2half2_rn(a.x, a.z);
    h[1] = __floats2half2_rn(b.x, b.z);
    h[2] = __floats2half2_rn(c.x, c.z);
    h[3] = __floats2half2_rn(d.x, d.z);
    // 8 halves = 16 B, aligned (voxel base 8i -> byte offset 16i).
    reinterpret_cast<uint4*>(g_xh)[i] = *reinterpret_cast<uint4*>(h);
}

// ---------------------------------------------------------------------------
__device__ __forceinline__ float clampi_f(int v, int hi, int* out_i) {
    int c = v < 0 ? 0 : (v > hi ? hi : v);
    *out_i = c;
    return (float)c;
}

__global__ void __launch_bounds__(THREADS)
deform3d_kernel(const float4* __restrict__ def4,
                float* __restrict__ out) {
    __shared__ float sdef[THREADS * 3];   // 3072 B

    int tid = threadIdx.x;
    int v   = blockIdx.x * THREADS + tid;   // grid exact: v < NT always

    // Stage this block's 768 def floats: 192 coalesced float4 loads.
    if (tid < 192) {
        reinterpret_cast<float4*>(sdef)[tid] =
            __ldcs(&def4[(size_t)blockIdx.x * 192 + tid]);
    }
    __syncthreads();

    // Stride-3 LDS across lanes: 3 coprime 32 -> conflict-free.
    float dx = sdef[3 * tid + 0];
    float dy = sdef[3 * tid + 1];
    float dz = sdef[3 * tid + 2];

    int b   = v / N;
    int r   = v - b * N;
    int iy  = r / WD;
    int rem = r - iy * WD;
    int ix  = rem / D;
    int iz  = rem - ix * D;

    float x = (float)ix + dx;
    float y = (float)iy + dy;
    float z = (float)iz + dz;

    int x0i = (int)floorf(x);
    int y0i = (int)floorf(y);
    int z0i = (int)floorf(z);

    int x0, x1, y0, y1, z0, z1;
    float x0f = clampi_f(x0i,     W - 1, &x0);
    float x1f = clampi_f(x0i + 1, W - 1, &x1);
    float y0f = clampi_f(y0i,     H - 1, &y0);
    float y1f = clampi_f(y0i + 1, H - 1, &y1);
    float z0f = clampi_f(z0i,     D - 1, &z0);
    float z1f = clampi_f(z0i + 1, D - 1, &z1);

    // Weights from CLAMPED coords (reference clips before computing weights).
    float wx0 = x - x0f, wx1 = x1f - x;
    float wy0 = y - y0f, wy1 = y1f - y;
    float wz0 = z - z0f, wz1 = z1f - z;

    const __half* Xb = g_xh + (size_t)b * N;
    int oy0 = y0 * WD, oy1 = y1 * WD;
    int ox0 = x0 * D,  ox1 = x1 * D;
    int i00 = oy0 + ox0;
    int i01 = oy0 + ox1;
    int i10 = oy1 + ox0;
    int i11 = oy1 + ox1;

    float p000 = __half2float(__ldg(&Xb[i00 + z0]));
    float p001 = __half2float(__ldg(&Xb[i00 + z1]));
    float p010 = __half2float(__ldg(&Xb[i01 + z0]));
    float p011 = __half2float(__ldg(&Xb[i01 + z1]));
    float p100 = __half2float(__ldg(&Xb[i10 + z0]));
    float p101 = __half2float(__ldg(&Xb[i10 + z1]));
    float p110 = __half2float(__ldg(&Xb[i11 + z0]));
    float p111 = __half2float(__ldg(&Xb[i11 + z1]));

    float c00 = wz1 * p000 + wz0 * p001;
    float c01 = wz1 * p010 + wz0 * p011;
    float c10 = wz1 * p100 + wz0 * p101;
    float c11 = wz1 * p110 + wz0 * p111;

    float c0 = wx1 * c00 + wx0 * c01;
    float c1 = wx1 * c10 + wx0 * c11;

    // Streaming store: keep compacted X resident in L2.
    __stcs(&out[v], wy1 * c0 + wy0 * c1);
}

extern "C" void kernel_launch(void* const* d_in, const int* in_sizes, int n_in,
                              void* d_out, int out_size) {
    const float* X   = (const float*)d_in[0];
    const float* def = (const float*)d_in[1];

    constexpr int pre_blocks = (PRE_ITEMS + 255) / 256;   // 4800

    compact_kernel<<<pre_blocks, 256>>>(reinterpret_cast<const float4*>(X));
    deform3d_kernel<<<MAIN_BLOCKS, THREADS>>>(
        reinterpret_cast<const float4*>(def),
        (float*)d_out);
}

// round 8
// speedup vs baseline: 1.2978x; 1.2978x over previous
#include <cuda_runtime.h>
#include <cuda_fp16.h>
#include <cstdint>

// SpatialDeformer3D: trilinear warp of X[...,0] by per-voxel deformation.
// Shapes fixed: B=2, H=160, W=192, D=160.
//
// R8: parity-duplicated fp16 volume -> each z-pair gather is ONE half2 LDG.
//   g_even[i] = ch0[i]          (half2 k covers elements 2k, 2k+1)
//   g_odd[i]  = ch0[i+1]        (half2 k covers elements 2k+1, 2k+2)
//   For element index e (any parity): copy = e&1, pair = e>>1,
//   .x = ch0[e], .y = ch0[e+1].
// Degenerate z (z0 floor outside [0,D-2]) contributes exactly 0 in the
// reference (wz0+wz1 = z1f-z0f = 0) -> zero the z-weights explicitly.
// Skeleton = R6 (best main-kernel so far): 2 vox/thread, float2 def, float2 out.

namespace {
constexpr int B  = 2;
constexpr int H  = 160;
constexpr int W  = 192;
constexpr int D  = 160;
constexpr int WD = W * D;            // 30720
constexpr int N  = H * W * D;        // 4,915,200 per batch
constexpr int NT = B * N;            // 9,830,400 total voxels
constexpr int PRE_ITEMS = NT / 8;    // 8 voxels per pre-pass thread
}

// Two fp16 copies, 19.7 MB each (39.3 MB total). Static scratch (no allocs).
__device__ __half g_even[NT];
__device__ __half g_odd[NT];

// ---------------------------------------------------------------------------
// Pre-pass: X interleaved f32 (ch0,ch1) -> g_even (ch0), g_odd (ch0 shifted).
__global__ void __launch_bounds__(256)
compact_kernel(const float4* __restrict__ X4) {
    int i = blockIdx.x * blockDim.x + threadIdx.x;   // [0, NT/8)
    if (i >= PRE_ITEMS) return;
    float4 a = X4[4 * i + 0];   // ch0 at .x,.z
    float4 b = X4[4 * i + 1];
    float4 c = X4[4 * i + 2];
    float4 d = X4[4 * i + 3];
    // one extra element for the shifted copy (clamped at the very end)
    float extra = (i + 1 < PRE_ITEMS) ? X4[4 * i + 4].x : d.z;

    __half2 he[4], ho[4];
    he[0] = __floats2half2_rn(a.x, a.z);
    he[1] = __floats2half2_rn(b.x, b.z);
    he[2] = __floats2half2_rn(c.x, c.z);
    he[3] = __floats2half2_rn(d.x, d.z);
    ho[0] = __floats2half2_rn(a.z, b.x);
    ho[1] = __floats2half2_rn(b.z, c.x);
    ho[2] = __floats2half2_rn(c.z, d.x);
    ho[3] = __floats2half2_rn(d.z, extra);

    reinterpret_cast<uint4*>(g_even)[i] = *reinterpret_cast<uint4*>(he);
    reinterpret_cast<uint4*>(g_odd)[i]  = *reinterpret_cast<uint4*>(ho);
}

// ---------------------------------------------------------------------------
__device__ __forceinline__ float clampi_f(int v, int hi, int* out_i) {
    int c = v < 0 ? 0 : (v > hi ? hi : v);
    *out_i = c;
    return (float)c;
}

__device__ __forceinline__ float sample_one(int bN, int ix, int iy, int iz,
                                            float dx, float dy, float dz) {
    float x = (float)ix + dx;
    float y = (float)iy + dy;
    float z = (float)iz + dz;

    int x0i = (int)floorf(x);
    int y0i = (int)floorf(y);
    int z0i = (int)floorf(z);

    // x / y: clamp; degenerate (x0==x1) cancels algebraically (wx0+wx1=0).
    int x0, x1, y0, y1;
    float x0f = clampi_f(x0i,     W - 1, &x0);
    float x1f = clampi_f(x0i + 1, W - 1, &x1);
    float y0f = clampi_f(y0i,     H - 1, &y0);
    float y1f = clampi_f(y0i + 1, H - 1, &y1);
    float wx0 = x - x0f, wx1 = x1f - x;
    float wy0 = y - y0f, wy1 = y1f - y;

    // z: pair (z0, z0+1) always adjacent when z0i in [0, D-2];
    // otherwise the reference's z-contribution is exactly zero.
    bool zok  = (z0i >= 0) && (z0i < D - 1);
    int  zz   = zok ? z0i : 0;
    float wz0 = zok ? (z - (float)z0i)        : 0.0f;
    float wz1 = zok ? ((float)z0i + 1.0f - z) : 0.0f;

    const __half2* gz = (zz & 1) ? reinterpret_cast<const __half2*>(g_odd)
                                 : reinterpret_cast<const __half2*>(g_even);

    int i00 = bN + y0 * WD + x0 * D;   // even (WD, D even, bN even)
    int i01 = bN + y0 * WD + x1 * D;
    int i10 = bN + y1 * WD + x0 * D;
    int i11 = bN + y1 * WD + x1 * D;

    __half2 h00 = __ldg(&gz[(i00 + zz) >> 1]);   // .x = [z0], .y = [z0+1]
    __half2 h01 = __ldg(&gz[(i01 + zz) >> 1]);
    __half2 h10 = __ldg(&gz[(i10 + zz) >> 1]);
    __half2 h11 = __ldg(&gz[(i11 + zz) >> 1]);

    float c00 = wz1 * __half2float(h00.x) + wz0 * __half2float(h00.y);
    float c01 = wz1 * __half2float(h01.x) + wz0 * __half2float(h01.y);
    float c10 = wz1 * __half2float(h10.x) + wz0 * __half2float(h10.y);
    float c11 = wz1 * __half2float(h11.x) + wz0 * __half2float(h11.y);

    float c0 = wx1 * c00 + wx0 * c01;
    float c1 = wx1 * c10 + wx0 * c11;

    return wy1 * c0 + wy0 * c1;
}

__global__ void __launch_bounds__(256)
deform3d_kernel(const float2* __restrict__ def2,
                float2* __restrict__ out2) {
    int t = blockIdx.x * blockDim.x + threadIdx.x;  // [0, NT/2)
    if (t >= NT / 2) return;

    int r2  = t * 2;
    int b   = r2 / N;
    int r   = r2 - b * N;
    int iy  = r / WD;
    int rem = r - iy * WD;
    int ix  = rem / D;
    int iz  = rem - ix * D;        // even; iz+1 < D

    float2 d0 = __ldcs(&def2[3 * t + 0]);   // (dxA, dyA)
    float2 d1 = __ldcs(&def2[3 * t + 1]);   // (dzA, dxB)
    float2 d2 = __ldcs(&def2[3 * t + 2]);   // (dyB, dzB)

    int bN = b * N;
    float2 o;
    o.x = sample_one(bN, ix, iy, iz,     d0.x, d0.y, d1.x);
    o.y = sample_one(bN, ix, iy, iz + 1, d1.y, d2.x, d2.y);

    __stcs(&out2[t], o);
}

extern "C" void kernel_launch(void* const* d_in, const int* in_sizes, int n_in,
                              void* d_out, int out_size) {
    const float* X   = (const float*)d_in[0];
    const float* def = (const float*)d_in[1];

    constexpr int threads = 256;
    constexpr int pre_blocks  = (PRE_ITEMS + threads - 1) / threads;   // 4800
    constexpr int main_blocks = (NT / 2 + threads - 1) / threads;      // 19200

    compact_kernel<<<pre_blocks, threads>>>(reinterpret_cast<const float4*>(X));
    deform3d_kernel<<<main_blocks, threads>>>(
        reinterpret_cast<const float2*>(def),
        reinterpret_cast<float2*>(d_out));
}